// round 8
// baseline (speedup 1.0000x reference)
#include <cuda_runtime.h>
#include <cstddef>

#define NN   2048
#define DIN  256

// Scratch (device globals — no allocation allowed in kernel_launch)
__device__ float g_proj[NN * DIN];            // 2 MB: [Q | K | V | R] per row
__device__ float g_S[(size_t)NN * NN];        // 16 MB: scale * Q @ K^T

// ---------------------------------------------------------------------------
// Generic C = alpha * A(MxK, lda) @ B^T(NxK, ldb), 64x64 tiles, K multiple of 64
// grid: (Ntiles, Mtiles), block: 256 threads, each thread computes 4x4
// ---------------------------------------------------------------------------
__global__ __launch_bounds__(256) void gemm_nt(
    const float* __restrict__ A, int lda,
    const float* __restrict__ B, int ldb,
    float* __restrict__ C, int ldc,
    int K, float alpha)
{
    __shared__ float As[64][65];
    __shared__ float Bs[64][65];
    const int tid = threadIdx.x;
    const int tx = tid & 15, ty = tid >> 4;
    const int rb = blockIdx.y * 64, cb = blockIdx.x * 64;

    float acc[4][4] = {};

    for (int kt = 0; kt < K; kt += 64) {
        #pragma unroll
        for (int it = 0; it < 4; it++) {
            int f  = tid + it * 256;          // 0..1023
            int r  = f >> 4;
            int c4 = (f & 15) << 2;
            float4 a = *(const float4*)(A + (size_t)(rb + r) * lda + kt + c4);
            As[r][c4 + 0] = a.x; As[r][c4 + 1] = a.y;
            As[r][c4 + 2] = a.z; As[r][c4 + 3] = a.w;
            float4 b = *(const float4*)(B + (size_t)(cb + r) * ldb + kt + c4);
            Bs[r][c4 + 0] = b.x; Bs[r][c4 + 1] = b.y;
            Bs[r][c4 + 2] = b.z; Bs[r][c4 + 3] = b.w;
        }
        __syncthreads();
        #pragma unroll 16
        for (int k = 0; k < 64; k++) {
            float ai[4], bj[4];
            #pragma unroll
            for (int i = 0; i < 4; i++) ai[i] = As[ty * 4 + i][k];
            #pragma unroll
            for (int j = 0; j < 4; j++) bj[j] = Bs[tx * 4 + j][k];
            #pragma unroll
            for (int i = 0; i < 4; i++)
                #pragma unroll
                for (int j = 0; j < 4; j++)
                    acc[i][j] = fmaf(ai[i], bj[j], acc[i][j]);
        }
        __syncthreads();
    }

    #pragma unroll
    for (int i = 0; i < 4; i++)
        #pragma unroll
        for (int j = 0; j < 4; j++)
            C[(size_t)(rb + ty * 4 + i) * ldc + cb + tx * 4 + j] = alpha * acc[i][j];
}

// ---------------------------------------------------------------------------
// Main fused kernel: per block, G=4 query rows.
//  Phase 1: w[j][g] = S[i_g][j] + scale * dot(R[i_g], D[i_g, j, :])
//  Phase 2: per-row softmax over j (in shared)
//  Phase 3: out[i_g] = softmax @ V
// ---------------------------------------------------------------------------
__global__ __launch_bounds__(256) void attn_main(
    const float* __restrict__ Dm,     // (N, N, 64)
    const float* __restrict__ proj,   // (N, 256)
    const float* __restrict__ S,      // (N, N), already scaled
    float* __restrict__ out)          // (N, 64)
{
    __shared__ __align__(16) float wsh[NN * 4];   // [j][g], 32 KB
    __shared__ float rbuf[9];
    __shared__ float inv[4];

    const int tid  = threadIdx.x;
    const int lane = tid & 31;
    const int w    = tid >> 5;
    const int i0   = blockIdx.x << 2;
    const float scale = 0.08838834764831845f;     // 1/sqrt(DK+DR)

    // ---------------- Phase 1: weights ----------------
    {
        const int g     = w & 3;                 // this warp's query row
        const int jbase = (w >> 2) * (NN / 2);   // which half of j
        const int sub   = lane >> 4;             // 2 j's per warp
        const int kq    = (lane & 15) << 2;      // 4 elems per lane
        const int irow  = i0 + g;

        const float4 r4 = *(const float4*)(proj + irow * DIN + 192 + kq);
        const float* Srow = S + (size_t)irow * NN;
        const float4* dp  = (const float4*)(Dm + ((size_t)irow * NN + jbase + sub) * 64 + kq);

        #pragma unroll 8
        for (int t = 0; t < NN / 4; t++) {       // 512 iters, 2 j's each
            float4 d4 = *dp;
            dp += 32;                            // advance 2 j rows
            float p = r4.x * d4.x + r4.y * d4.y;
            p = fmaf(r4.z, d4.z, p);
            p = fmaf(r4.w, d4.w, p);
            p += __shfl_xor_sync(0xffffffffu, p, 8);
            p += __shfl_xor_sync(0xffffffffu, p, 4);
            p += __shfl_xor_sync(0xffffffffu, p, 2);
            p += __shfl_xor_sync(0xffffffffu, p, 1);
            if ((lane & 15) == 0) {
                int j = jbase + 2 * t + sub;
                wsh[(j << 2) + g] = fmaf(p, scale, Srow[j]);
            }
        }
    }
    __syncthreads();

    // ---------------- Phase 2: softmax per g ----------------
    #pragma unroll 1
    for (int gg = 0; gg < 4; gg++) {
        float m = -1e30f;
        for (int j = tid; j < NN; j += 256) m = fmaxf(m, wsh[(j << 2) + gg]);
        #pragma unroll
        for (int o = 16; o; o >>= 1) m = fmaxf(m, __shfl_xor_sync(0xffffffffu, m, o));
        if (lane == 0) rbuf[w] = m;
        __syncthreads();
        if (tid == 0) {
            float mm = rbuf[0];
            #pragma unroll
            for (int q = 1; q < 8; q++) mm = fmaxf(mm, rbuf[q]);
            rbuf[8] = mm;
        }
        __syncthreads();
        m = rbuf[8];

        float s = 0.f;
        for (int j = tid; j < NN; j += 256) {
            float e = __expf(wsh[(j << 2) + gg] - m);
            wsh[(j << 2) + gg] = e;
            s += e;
        }
        #pragma unroll
        for (int o = 16; o; o >>= 1) s += __shfl_xor_sync(0xffffffffu, s, o);
        __syncthreads();
        if (lane == 0) rbuf[w] = s;
        __syncthreads();
        if (tid == 0) {
            float ss = 0.f;
            #pragma unroll
            for (int q = 0; q < 8; q++) ss += rbuf[q];
            inv[gg] = 1.0f / ss;
        }
        __syncthreads();
    }

    // ---------------- Phase 3: attn @ V ----------------
    const int d = tid & 63;
    const int h = tid >> 6;     // 4 j-interleaved groups
    float a0 = 0.f, a1 = 0.f, a2 = 0.f, a3 = 0.f;
    const float* Vp = proj + 128 + d;
    #pragma unroll 4
    for (int j = h; j < NN; j += 4) {
        float  v = Vp[(size_t)j * DIN];
        float4 e = *(const float4*)(wsh + (j << 2));
        a0 = fmaf(e.x, v, a0);
        a1 = fmaf(e.y, v, a1);
        a2 = fmaf(e.z, v, a2);
        a3 = fmaf(e.w, v, a3);
    }
    __syncthreads();
    // partial reduce across the 4 h-groups (reuse wsh)
    wsh[(h * 4 + 0) * 64 + d] = a0;
    wsh[(h * 4 + 1) * 64 + d] = a1;
    wsh[(h * 4 + 2) * 64 + d] = a2;
    wsh[(h * 4 + 3) * 64 + d] = a3;
    __syncthreads();
    {
        const int g = h;   // reuse thread mapping: thread (g, d)
        float r = wsh[(0 * 4 + g) * 64 + d] + wsh[(1 * 4 + g) * 64 + d]
                + wsh[(2 * 4 + g) * 64 + d] + wsh[(3 * 4 + g) * 64 + d];
        out[(size_t)(i0 + g) * 64 + d] = r * inv[g];
    }
}

// ---------------------------------------------------------------------------
extern "C" void kernel_launch(void* const* d_in, const int* in_sizes, int n_in,
                              void* d_out, int out_size)
{
    (void)out_size;
    const float *H = nullptr, *Dm = nullptr, *Wp = nullptr;
    for (int i = 0; i < n_in; i++) {
        if      (in_sizes[i] == NN * DIN)  H  = (const float*)d_in[i];
        else if (in_sizes[i] == DIN * DIN) Wp = (const float*)d_in[i];
        else                               Dm = (const float*)d_in[i];
    }

    float* proj = nullptr;
    float* Sp   = nullptr;
    cudaGetSymbolAddress((void**)&proj, g_proj);
    cudaGetSymbolAddress((void**)&Sp,   g_S);

    const float scale = 0.08838834764831845f;   // 1/sqrt(128)

    // 1) proj = H @ W^T   (2048 x 256)
    gemm_nt<<<dim3(DIN / 64, NN / 64), 256>>>(H, DIN, Wp, DIN, proj, DIN, DIN, 1.0f);
    // 2) S = scale * Q @ K^T   (2048 x 2048)
    gemm_nt<<<dim3(NN / 64, NN / 64), 256>>>(proj, DIN, proj + 64, DIN, Sp, NN, 64, scale);
    // 3) fused RD + softmax + @V
    attn_main<<<NN / 4, 256>>>(Dm, proj, Sp, (float*)d_out);
}

// round 9
// speedup vs baseline: 1.1851x; 1.1851x over previous
#include <cuda_runtime.h>
#include <cstddef>

#define NN   2048
#define DIN  256

// Scratch (device globals — no allocation allowed in kernel_launch)
__device__ float g_proj[NN * DIN];            // 2 MB: [Q | K | V | R] per row
__device__ float g_S[(size_t)NN * NN];        // 16 MB: scale * Q @ K^T

// ---------------------------------------------------------------------------
// C = alpha * A(MxK, lda) @ B^T(NxK, ldb), 64x64 tiles, 256 thr, 4x4/thread
// ---------------------------------------------------------------------------
__global__ __launch_bounds__(256) void gemm_nt(
    const float* __restrict__ A, int lda,
    const float* __restrict__ B, int ldb,
    float* __restrict__ C, int ldc,
    int K, float alpha)
{
    __shared__ float As[64][65];
    __shared__ float Bs[64][65];
    const int tid = threadIdx.x;
    const int tx = tid & 15, ty = tid >> 4;
    const int rb = blockIdx.y * 64, cb = blockIdx.x * 64;

    float acc[4][4] = {};

    for (int kt = 0; kt < K; kt += 64) {
        #pragma unroll
        for (int it = 0; it < 4; it++) {
            int f  = tid + it * 256;
            int r  = f >> 4;
            int c4 = (f & 15) << 2;
            float4 a = *(const float4*)(A + (size_t)(rb + r) * lda + kt + c4);
            As[r][c4 + 0] = a.x; As[r][c4 + 1] = a.y;
            As[r][c4 + 2] = a.z; As[r][c4 + 3] = a.w;
            float4 b = *(const float4*)(B + (size_t)(cb + r) * ldb + kt + c4);
            Bs[r][c4 + 0] = b.x; Bs[r][c4 + 1] = b.y;
            Bs[r][c4 + 2] = b.z; Bs[r][c4 + 3] = b.w;
        }
        __syncthreads();
        #pragma unroll 16
        for (int k = 0; k < 64; k++) {
            float ai[4], bj[4];
            #pragma unroll
            for (int i = 0; i < 4; i++) ai[i] = As[ty * 4 + i][k];
            #pragma unroll
            for (int j = 0; j < 4; j++) bj[j] = Bs[tx * 4 + j][k];
            #pragma unroll
            for (int i = 0; i < 4; i++)
                #pragma unroll
                for (int j = 0; j < 4; j++)
                    acc[i][j] = fmaf(ai[i], bj[j], acc[i][j]);
        }
        __syncthreads();
    }

    #pragma unroll
    for (int i = 0; i < 4; i++)
        #pragma unroll
        for (int j = 0; j < 4; j++)
            C[(size_t)(rb + ty * 4 + i) * ldc + cb + tx * 4 + j] = alpha * acc[i][j];
}

// ---------------------------------------------------------------------------
// Same GEMM with 64x32 tiles (4x2/thread) -> 2x the grid for small-N matrices
// ---------------------------------------------------------------------------
__global__ __launch_bounds__(256) void gemm_nt32(
    const float* __restrict__ A, int lda,
    const float* __restrict__ B, int ldb,
    float* __restrict__ C, int ldc,
    int K, float alpha)
{
    __shared__ float As[64][65];
    __shared__ float Bs[32][65];
    const int tid = threadIdx.x;
    const int tx = tid & 15, ty = tid >> 4;
    const int rb = blockIdx.y * 64, cb = blockIdx.x * 32;

    float acc[4][2] = {};

    for (int kt = 0; kt < K; kt += 64) {
        #pragma unroll
        for (int it = 0; it < 4; it++) {
            int f  = tid + it * 256;
            int r  = f >> 4;
            int c4 = (f & 15) << 2;
            float4 a = *(const float4*)(A + (size_t)(rb + r) * lda + kt + c4);
            As[r][c4 + 0] = a.x; As[r][c4 + 1] = a.y;
            As[r][c4 + 2] = a.z; As[r][c4 + 3] = a.w;
        }
        #pragma unroll
        for (int it = 0; it < 2; it++) {
            int f  = tid + it * 256;
            int r  = f >> 4;
            int c4 = (f & 15) << 2;
            float4 b = *(const float4*)(B + (size_t)(cb + r) * ldb + kt + c4);
            Bs[r][c4 + 0] = b.x; Bs[r][c4 + 1] = b.y;
            Bs[r][c4 + 2] = b.z; Bs[r][c4 + 3] = b.w;
        }
        __syncthreads();
        #pragma unroll 16
        for (int k = 0; k < 64; k++) {
            float ai[4], bj[2];
            #pragma unroll
            for (int i = 0; i < 4; i++) ai[i] = As[ty * 4 + i][k];
            #pragma unroll
            for (int j = 0; j < 2; j++) bj[j] = Bs[tx * 2 + j][k];
            #pragma unroll
            for (int i = 0; i < 4; i++)
                #pragma unroll
                for (int j = 0; j < 2; j++)
                    acc[i][j] = fmaf(ai[i], bj[j], acc[i][j]);
        }
        __syncthreads();
    }

    #pragma unroll
    for (int i = 0; i < 4; i++)
        #pragma unroll
        for (int j = 0; j < 2; j++)
            C[(size_t)(rb + ty * 4 + i) * ldc + cb + tx * 2 + j] = alpha * acc[i][j];
}

// ---------------------------------------------------------------------------
// Main fused kernel: per block G=4 query rows, 512 threads (16 warps),
// grid 512 -> single wave at 4 blocks/SM.
//  Phase 1: w[j][g] = S[i_g][j] + scale * dot(R[i_g], D[i_g, j, :])
//           8-lane/j scheme: 4 j per warp-iteration, 3 SHFLs.
//  Phase 2: softmax, the 4 rows handled by 4 parallel 128-thread groups.
//  Phase 3: out[i_g] = softmax @ V with 8 j-interleaved partial groups.
// ---------------------------------------------------------------------------
__global__ __launch_bounds__(512, 4) void attn_main(
    const float* __restrict__ Dm,     // (N, N, 64)
    const float* __restrict__ proj,   // (N, 256)
    const float* __restrict__ S,      // (N, N), already scaled
    float* __restrict__ out)          // (N, 64)
{
    __shared__ __align__(16) float wsh[NN * 4];   // [j][g], 32 KB
    __shared__ float red[4][8];                   // [g][warp-in-group] (max, then sum)
    __shared__ float inv4[4];

    const int tid  = threadIdx.x;
    const int lane = tid & 31;
    const int w    = tid >> 5;                    // 0..15
    const int i0   = blockIdx.x << 2;
    const float scale = 0.08838834764831845f;     // 1/sqrt(DK+DR)

    // ---------------- Phase 1: weights ----------------
    {
        const int g    = w & 3;                   // query row within block
        const int jq   = w >> 2;                  // j quarter (0..3), 512 j each
        const int jj   = lane >> 3;               // which of 4 j's this lane helps
        const int rq   = lane & 7;                // r chunk: this lane does r = rq*8..rq*8+7
        const int irow = i0 + g;
        const int j0   = jq * 512;

        const float4 r0 = *(const float4*)(proj + irow * DIN + 192 + rq * 8);
        const float4 r1 = *(const float4*)(proj + irow * DIN + 192 + rq * 8 + 4);
        const float* Srow = S + (size_t)irow * NN;
        const float4* dp  = (const float4*)(Dm + ((size_t)irow * NN + j0 + jj) * 64 + rq * 8);

        #pragma unroll 4
        for (int t = 0; t < 128; t++) {           // 4 j per iteration
            float4 d0 = dp[0];
            float4 d1 = dp[1];
            dp += 64;                             // advance 4 j rows
            float p = r0.x * d0.x + r0.y * d0.y;
            p = fmaf(r0.z, d0.z, p);
            p = fmaf(r0.w, d0.w, p);
            p = fmaf(r1.x, d1.x, p);
            p = fmaf(r1.y, d1.y, p);
            p = fmaf(r1.z, d1.z, p);
            p = fmaf(r1.w, d1.w, p);
            p += __shfl_xor_sync(0xffffffffu, p, 4);
            p += __shfl_xor_sync(0xffffffffu, p, 2);
            p += __shfl_xor_sync(0xffffffffu, p, 1);
            if (rq == 0) {
                int j = j0 + 4 * t + jj;
                wsh[(j << 2) + g] = fmaf(p, scale, Srow[j]);
            }
        }
    }
    __syncthreads();

    // ---------------- Phase 2: softmax, 4 rows in parallel ----------------
    {
        const int gg = tid >> 7;                  // row handled by this 128-thread group
        const int tl = tid & 127;
        const int wg = (tid >> 5) & 3;            // warp within group

        float m = -1e30f;
        #pragma unroll
        for (int u = 0; u < 16; u++)
            m = fmaxf(m, wsh[((tl + u * 128) << 2) + gg]);
        #pragma unroll
        for (int o = 16; o; o >>= 1)
            m = fmaxf(m, __shfl_xor_sync(0xffffffffu, m, o));
        if (lane == 0) red[gg][wg] = m;
        __syncthreads();
        m = fmaxf(fmaxf(red[gg][0], red[gg][1]), fmaxf(red[gg][2], red[gg][3]));

        float s = 0.f;
        #pragma unroll
        for (int u = 0; u < 16; u++) {
            int idx = ((tl + u * 128) << 2) + gg;
            float e = __expf(wsh[idx] - m);
            wsh[idx] = e;
            s += e;
        }
        #pragma unroll
        for (int o = 16; o; o >>= 1)
            s += __shfl_xor_sync(0xffffffffu, s, o);
        __syncthreads();
        if (lane == 0) red[gg][4 + wg] = s;
        __syncthreads();
        if (tid < 4)
            inv4[tid] = 1.0f / (red[tid][4] + red[tid][5] + red[tid][6] + red[tid][7]);
        __syncthreads();
    }

    // ---------------- Phase 3: attn @ V ----------------
    {
        const int d = tid & 63;
        const int h = tid >> 6;                   // 8 j-interleaved groups
        float a0 = 0.f, a1 = 0.f, a2 = 0.f, a3 = 0.f;
        const float* Vp = proj + 128 + d;
        #pragma unroll 4
        for (int j = h; j < NN; j += 8) {
            float  v = __ldg(Vp + (size_t)j * DIN);
            float4 e = *(const float4*)(wsh + (j << 2));
            a0 = fmaf(e.x, v, a0);
            a1 = fmaf(e.y, v, a1);
            a2 = fmaf(e.z, v, a2);
            a3 = fmaf(e.w, v, a3);
        }
        __syncthreads();                          // done reading weights
        wsh[((h << 2) + 0) * 64 + d] = a0;
        wsh[((h << 2) + 1) * 64 + d] = a1;
        wsh[((h << 2) + 2) * 64 + d] = a2;
        wsh[((h << 2) + 3) * 64 + d] = a3;
        __syncthreads();
        if (tid < 256) {
            const int g2 = tid >> 6, d2 = tid & 63;
            float r = 0.f;
            #pragma unroll
            for (int hh = 0; hh < 8; hh++)
                r += wsh[((hh << 2) + g2) * 64 + d2];
            out[(size_t)(i0 + g2) * 64 + d2] = r * inv4[g2];
        }
    }
}

// ---------------------------------------------------------------------------
extern "C" void kernel_launch(void* const* d_in, const int* in_sizes, int n_in,
                              void* d_out, int out_size)
{
    (void)out_size;
    const float *H = nullptr, *Dm = nullptr, *Wp = nullptr;
    for (int i = 0; i < n_in; i++) {
        if      (in_sizes[i] == NN * DIN)  H  = (const float*)d_in[i];
        else if (in_sizes[i] == DIN * DIN) Wp = (const float*)d_in[i];
        else                               Dm = (const float*)d_in[i];
    }

    float* proj = nullptr;
    float* Sp   = nullptr;
    cudaGetSymbolAddress((void**)&proj, g_proj);
    cudaGetSymbolAddress((void**)&Sp,   g_S);

    const float scale = 0.08838834764831845f;   // 1/sqrt(128)

    // 1) proj = H @ W^T   (2048 x 256) — 64x32 tiles -> 256 blocks
    gemm_nt32<<<dim3(DIN / 32, NN / 64), 256>>>(H, DIN, Wp, DIN, proj, DIN, DIN, 1.0f);
    // 2) S = scale * Q @ K^T   (2048 x 2048)
    gemm_nt<<<dim3(NN / 64, NN / 64), 256>>>(proj, DIN, proj + 64, DIN, Sp, NN, 64, scale);
    // 3) fused RD + softmax + @V  — single wave: 512 blocks @ 4/SM
    attn_main<<<NN / 4, 512>>>(Dm, proj, Sp, (float*)d_out);
}

// round 10
// speedup vs baseline: 1.1867x; 1.0013x over previous
#include <cuda_runtime.h>
#include <cstddef>

#define NN   2048
#define DIN  256

// Scratch (device globals — no allocation allowed in kernel_launch)
__device__ float g_proj[NN * DIN];            // 2 MB: [Q | K | V | R] per row
__device__ float g_S[(size_t)NN * NN];        // 16 MB: scale * Q @ K^T

// ---------------------------------------------------------------------------
// C = alpha * A(MxK, lda) @ B^T(NxK, ldb), 64x64 tiles, 256 thr, 4x4/thread
// ---------------------------------------------------------------------------
__global__ __launch_bounds__(256) void gemm_nt(
    const float* __restrict__ A, int lda,
    const float* __restrict__ B, int ldb,
    float* __restrict__ C, int ldc,
    int K, float alpha)
{
    __shared__ float As[64][65];
    __shared__ float Bs[64][65];
    const int tid = threadIdx.x;
    const int tx = tid & 15, ty = tid >> 4;
    const int rb = blockIdx.y * 64, cb = blockIdx.x * 64;

    float acc[4][4] = {};

    for (int kt = 0; kt < K; kt += 64) {
        #pragma unroll
        for (int it = 0; it < 4; it++) {
            int f  = tid + it * 256;
            int r  = f >> 4;
            int c4 = (f & 15) << 2;
            float4 a = *(const float4*)(A + (size_t)(rb + r) * lda + kt + c4);
            As[r][c4 + 0] = a.x; As[r][c4 + 1] = a.y;
            As[r][c4 + 2] = a.z; As[r][c4 + 3] = a.w;
            float4 b = *(const float4*)(B + (size_t)(cb + r) * ldb + kt + c4);
            Bs[r][c4 + 0] = b.x; Bs[r][c4 + 1] = b.y;
            Bs[r][c4 + 2] = b.z; Bs[r][c4 + 3] = b.w;
        }
        __syncthreads();
        #pragma unroll 16
        for (int k = 0; k < 64; k++) {
            float ai[4], bj[4];
            #pragma unroll
            for (int i = 0; i < 4; i++) ai[i] = As[ty * 4 + i][k];
            #pragma unroll
            for (int j = 0; j < 4; j++) bj[j] = Bs[tx * 4 + j][k];
            #pragma unroll
            for (int i = 0; i < 4; i++)
                #pragma unroll
                for (int j = 0; j < 4; j++)
                    acc[i][j] = fmaf(ai[i], bj[j], acc[i][j]);
        }
        __syncthreads();
    }

    #pragma unroll
    for (int i = 0; i < 4; i++)
        #pragma unroll
        for (int j = 0; j < 4; j++)
            C[(size_t)(rb + ty * 4 + i) * ldc + cb + tx * 4 + j] = alpha * acc[i][j];
}

// ---------------------------------------------------------------------------
// Same GEMM with 64x32 tiles (4x2/thread) -> 2x the grid for small-N matrices
// ---------------------------------------------------------------------------
__global__ __launch_bounds__(256) void gemm_nt32(
    const float* __restrict__ A, int lda,
    const float* __restrict__ B, int ldb,
    float* __restrict__ C, int ldc,
    int K, float alpha)
{
    __shared__ float As[64][65];
    __shared__ float Bs[32][65];
    const int tid = threadIdx.x;
    const int tx = tid & 15, ty = tid >> 4;
    const int rb = blockIdx.y * 64, cb = blockIdx.x * 32;

    float acc[4][2] = {};

    for (int kt = 0; kt < K; kt += 64) {
        #pragma unroll
        for (int it = 0; it < 4; it++) {
            int f  = tid + it * 256;
            int r  = f >> 4;
            int c4 = (f & 15) << 2;
            float4 a = *(const float4*)(A + (size_t)(rb + r) * lda + kt + c4);
            As[r][c4 + 0] = a.x; As[r][c4 + 1] = a.y;
            As[r][c4 + 2] = a.z; As[r][c4 + 3] = a.w;
        }
        #pragma unroll
        for (int it = 0; it < 2; it++) {
            int f  = tid + it * 256;
            int r  = f >> 4;
            int c4 = (f & 15) << 2;
            float4 b = *(const float4*)(B + (size_t)(cb + r) * ldb + kt + c4);
            Bs[r][c4 + 0] = b.x; Bs[r][c4 + 1] = b.y;
            Bs[r][c4 + 2] = b.z; Bs[r][c4 + 3] = b.w;
        }
        __syncthreads();
        #pragma unroll 16
        for (int k = 0; k < 64; k++) {
            float ai[4], bj[2];
            #pragma unroll
            for (int i = 0; i < 4; i++) ai[i] = As[ty * 4 + i][k];
            #pragma unroll
            for (int j = 0; j < 2; j++) bj[j] = Bs[tx * 2 + j][k];
            #pragma unroll
            for (int i = 0; i < 4; i++)
                #pragma unroll
                for (int j = 0; j < 2; j++)
                    acc[i][j] = fmaf(ai[i], bj[j], acc[i][j]);
        }
        __syncthreads();
    }

    #pragma unroll
    for (int i = 0; i < 4; i++)
        #pragma unroll
        for (int j = 0; j < 2; j++)
            C[(size_t)(rb + ty * 4 + i) * ldc + cb + tx * 2 + j] = alpha * acc[i][j];
}

// ---------------------------------------------------------------------------
// Main fused kernel: per block G=4 query rows, 512 threads (16 warps),
// grid 512 -> single wave at 4 blocks/SM.
//  Phase 1: w[j][g] = S[i_g][j] + scale * dot(R[i_g], D[i_g, j, :])
//           8-lane/j scheme: 4 j per warp-iteration, 3 SHFLs.
//  Phase 2: softmax, the 4 rows handled by 4 parallel 128-thread groups.
//  Phase 3: out[i_g] = softmax @ V with 8 j-interleaved partial groups.
// ---------------------------------------------------------------------------
__global__ __launch_bounds__(512, 4) void attn_main(
    const float* __restrict__ Dm,     // (N, N, 64)
    const float* __restrict__ proj,   // (N, 256)
    const float* __restrict__ S,      // (N, N), already scaled
    float* __restrict__ out)          // (N, 64)
{
    __shared__ __align__(16) float wsh[NN * 4];   // [j][g], 32 KB
    __shared__ float red[4][8];                   // [g][warp-in-group] (max, then sum)
    __shared__ float inv4[4];

    const int tid  = threadIdx.x;
    const int lane = tid & 31;
    const int w    = tid >> 5;                    // 0..15
    const int i0   = blockIdx.x << 2;
    const float scale = 0.08838834764831845f;     // 1/sqrt(DK+DR)

    // ---------------- Phase 1: weights ----------------
    {
        const int g    = w & 3;                   // query row within block
        const int jq   = w >> 2;                  // j quarter (0..3), 512 j each
        const int jj   = lane >> 3;               // which of 4 j's this lane helps
        const int rq   = lane & 7;                // r chunk: this lane does r = rq*8..rq*8+7
        const int irow = i0 + g;
        const int j0   = jq * 512;

        const float4 r0 = *(const float4*)(proj + irow * DIN + 192 + rq * 8);
        const float4 r1 = *(const float4*)(proj + irow * DIN + 192 + rq * 8 + 4);
        const float* Srow = S + (size_t)irow * NN;
        const float4* dp  = (const float4*)(Dm + ((size_t)irow * NN + j0 + jj) * 64 + rq * 8);

        #pragma unroll 4
        for (int t = 0; t < 128; t++) {           // 4 j per iteration
            float4 d0 = dp[0];
            float4 d1 = dp[1];
            dp += 64;                             // advance 4 j rows
            float p = r0.x * d0.x + r0.y * d0.y;
            p = fmaf(r0.z, d0.z, p);
            p = fmaf(r0.w, d0.w, p);
            p = fmaf(r1.x, d1.x, p);
            p = fmaf(r1.y, d1.y, p);
            p = fmaf(r1.z, d1.z, p);
            p = fmaf(r1.w, d1.w, p);
            p += __shfl_xor_sync(0xffffffffu, p, 4);
            p += __shfl_xor_sync(0xffffffffu, p, 2);
            p += __shfl_xor_sync(0xffffffffu, p, 1);
            if (rq == 0) {
                int j = j0 + 4 * t + jj;
                wsh[(j << 2) + g] = fmaf(p, scale, Srow[j]);
            }
        }
    }
    __syncthreads();

    // ---------------- Phase 2: softmax, 4 rows in parallel ----------------
    {
        const int gg = tid >> 7;                  // row handled by this 128-thread group
        const int tl = tid & 127;
        const int wg = (tid >> 5) & 3;            // warp within group

        float m = -1e30f;
        #pragma unroll
        for (int u = 0; u < 16; u++)
            m = fmaxf(m, wsh[((tl + u * 128) << 2) + gg]);
        #pragma unroll
        for (int o = 16; o; o >>= 1)
            m = fmaxf(m, __shfl_xor_sync(0xffffffffu, m, o));
        if (lane == 0) red[gg][wg] = m;
        __syncthreads();
        m = fmaxf(fmaxf(red[gg][0], red[gg][1]), fmaxf(red[gg][2], red[gg][3]));

        float s = 0.f;
        #pragma unroll
        for (int u = 0; u < 16; u++) {
            int idx = ((tl + u * 128) << 2) + gg;
            float e = __expf(wsh[idx] - m);
            wsh[idx] = e;
            s += e;
        }
        #pragma unroll
        for (int o = 16; o; o >>= 1)
            s += __shfl_xor_sync(0xffffffffu, s, o);
        __syncthreads();
        if (lane == 0) red[gg][4 + wg] = s;
        __syncthreads();
        if (tid < 4)
            inv4[tid] = 1.0f / (red[tid][4] + red[tid][5] + red[tid][6] + red[tid][7]);
        __syncthreads();
    }

    // ---------------- Phase 3: attn @ V ----------------
    {
        const int d = tid & 63;
        const int h = tid >> 6;                   // 8 j-interleaved groups
        float a0 = 0.f, a1 = 0.f, a2 = 0.f, a3 = 0.f;
        const float* Vp = proj + 128 + d;
        #pragma unroll 4
        for (int j = h; j < NN; j += 8) {
            float  v = __ldg(Vp + (size_t)j * DIN);
            float4 e = *(const float4*)(wsh + (j << 2));
            a0 = fmaf(e.x, v, a0);
            a1 = fmaf(e.y, v, a1);
            a2 = fmaf(e.z, v, a2);
            a3 = fmaf(e.w, v, a3);
        }
        __syncthreads();                          // done reading weights
        wsh[((h << 2) + 0) * 64 + d] = a0;
        wsh[((h << 2) + 1) * 64 + d] = a1;
        wsh[((h << 2) + 2) * 64 + d] = a2;
        wsh[((h << 2) + 3) * 64 + d] = a3;
        __syncthreads();
        if (tid < 256) {
            const int g2 = tid >> 6, d2 = tid & 63;
            float r = 0.f;
            #pragma unroll
            for (int hh = 0; hh < 8; hh++)
                r += wsh[((hh << 2) + g2) * 64 + d2];
            out[(size_t)(i0 + g2) * 64 + d2] = r * inv4[g2];
        }
    }
}

// ---------------------------------------------------------------------------
extern "C" void kernel_launch(void* const* d_in, const int* in_sizes, int n_in,
                              void* d_out, int out_size)
{
    (void)out_size;
    const float *H = nullptr, *Dm = nullptr, *Wp = nullptr;
    for (int i = 0; i < n_in; i++) {
        if      (in_sizes[i] == NN * DIN)  H  = (const float*)d_in[i];
        else if (in_sizes[i] == DIN * DIN) Wp = (const float*)d_in[i];
        else                               Dm = (const float*)d_in[i];
    }

    float* proj = nullptr;
    float* Sp   = nullptr;
    cudaGetSymbolAddress((void**)&proj, g_proj);
    cudaGetSymbolAddress((void**)&Sp,   g_S);

    const float scale = 0.08838834764831845f;   // 1/sqrt(128)

    // 1) proj = H @ W^T   (2048 x 256) — 64x32 tiles -> 256 blocks
    gemm_nt32<<<dim3(DIN / 32, NN / 64), 256>>>(H, DIN, Wp, DIN, proj, DIN, DIN, 1.0f);
    // 2) S = scale * Q @ K^T   (2048 x 2048)
    gemm_nt<<<dim3(NN / 64, NN / 64), 256>>>(proj, DIN, proj + 64, DIN, Sp, NN, 64, scale);
    // 3) fused RD + softmax + @V  — single wave: 512 blocks @ 4/SM
    attn_main<<<NN / 4, 512>>>(Dm, proj, Sp, (float*)d_out);
}

// round 11
// speedup vs baseline: 1.2398x; 1.0448x over previous
#include <cuda_runtime.h>
#include <cstddef>

#define NN   2048
#define DIN  256

// Scratch (device global — no allocation allowed in kernel_launch)
__device__ float g_proj[NN * DIN];            // 2 MB: [Q | K | V | R] per row

// ---------------------------------------------------------------------------
// C = alpha * A(MxK, lda) @ B^T(NxK, ldb), 64x32 tiles (4x2/thread), 256 thr
// ---------------------------------------------------------------------------
__global__ __launch_bounds__(256) void gemm_nt32(
    const float* __restrict__ A, int lda,
    const float* __restrict__ B, int ldb,
    float* __restrict__ C, int ldc,
    int K, float alpha)
{
    __shared__ float As[64][65];
    __shared__ float Bs[32][65];
    const int tid = threadIdx.x;
    const int tx = tid & 15, ty = tid >> 4;
    const int rb = blockIdx.y * 64, cb = blockIdx.x * 32;

    float acc[4][2] = {};

    for (int kt = 0; kt < K; kt += 64) {
        #pragma unroll
        for (int it = 0; it < 4; it++) {
            int f  = tid + it * 256;
            int r  = f >> 4;
            int c4 = (f & 15) << 2;
            float4 a = *(const float4*)(A + (size_t)(rb + r) * lda + kt + c4);
            As[r][c4 + 0] = a.x; As[r][c4 + 1] = a.y;
            As[r][c4 + 2] = a.z; As[r][c4 + 3] = a.w;
        }
        #pragma unroll
        for (int it = 0; it < 2; it++) {
            int f  = tid + it * 256;
            int r  = f >> 4;
            int c4 = (f & 15) << 2;
            float4 b = *(const float4*)(B + (size_t)(cb + r) * ldb + kt + c4);
            Bs[r][c4 + 0] = b.x; Bs[r][c4 + 1] = b.y;
            Bs[r][c4 + 2] = b.z; Bs[r][c4 + 3] = b.w;
        }
        __syncthreads();
        #pragma unroll 16
        for (int k = 0; k < 64; k++) {
            float ai[4], bj[2];
            #pragma unroll
            for (int i = 0; i < 4; i++) ai[i] = As[ty * 4 + i][k];
            #pragma unroll
            for (int j = 0; j < 2; j++) bj[j] = Bs[tx * 2 + j][k];
            #pragma unroll
            for (int i = 0; i < 4; i++)
                #pragma unroll
                for (int j = 0; j < 2; j++)
                    acc[i][j] = fmaf(ai[i], bj[j], acc[i][j]);
        }
        __syncthreads();
    }

    #pragma unroll
    for (int i = 0; i < 4; i++)
        #pragma unroll
        for (int j = 0; j < 2; j++)
            C[(size_t)(rb + ty * 4 + i) * ldc + cb + tx * 2 + j] = alpha * acc[i][j];
}

// ---------------------------------------------------------------------------
// Main fused kernel: per block G=4 query rows, 512 threads, grid 512
// (single wave at 4 blocks/SM).
//  Phase 1: w[j][g] = scale * ( Q[i_g].K[j] + R[i_g].D[i_g,j,:] )
//           Fused 128-dim dot [Q|R].[K|D]; 8-lane/j, 4 j per warp-iter,
//           one 3-shuffle reduction serves both dots. No S matrix at all.
//  Phase 2: softmax, 4 rows handled by 4 parallel 128-thread groups.
//  Phase 3: out[i_g] = softmax @ V with 8 j-interleaved partial groups.
// ---------------------------------------------------------------------------
__global__ __launch_bounds__(512, 4) void attn_main(
    const float* __restrict__ Dm,     // (N, N, 64)
    const float* __restrict__ proj,   // (N, 256) = [Q | K | V | R]
    float* __restrict__ out)          // (N, 64)
{
    __shared__ __align__(16) float wsh[NN * 4];   // [j][g], 32 KB
    __shared__ float red[4][8];                   // [g][warp-in-group]
    __shared__ float inv4[4];

    const int tid  = threadIdx.x;
    const int lane = tid & 31;
    const int w    = tid >> 5;                    // 0..15
    const int i0   = blockIdx.x << 2;
    const float scale = 0.08838834764831845f;     // 1/sqrt(DK+DR)

    // ---------------- Phase 1: weights (fused QK^T + RD) ----------------
    {
        const int g    = w & 3;                   // query row within block
        const int jq   = w >> 2;                  // j quarter (0..3), 512 j each
        const int jj   = lane >> 3;               // which of 4 j's this lane helps
        const int rq   = lane & 7;                // dim chunk: rq*8 .. rq*8+7
        const int irow = i0 + g;
        const int j0   = jq * 512;

        // persistent: Q chunk (cols 0..63) and R chunk (cols 192..255)
        const float4 q0 = *(const float4*)(proj + irow * DIN + rq * 8);
        const float4 q1 = *(const float4*)(proj + irow * DIN + rq * 8 + 4);
        const float4 r0 = *(const float4*)(proj + irow * DIN + 192 + rq * 8);
        const float4 r1 = *(const float4*)(proj + irow * DIN + 192 + rq * 8 + 4);

        const float4* dp = (const float4*)(Dm + ((size_t)irow * NN + j0 + jj) * 64 + rq * 8);
        const float4* kp = (const float4*)(proj + (size_t)(j0 + jj) * DIN + 64 + rq * 8);

        #pragma unroll 4
        for (int t = 0; t < 128; t++) {           // 4 j per iteration
            float4 d0 = dp[0];
            float4 d1 = dp[1];
            float4 k0 = kp[0];
            float4 k1 = kp[1];
            dp += 64;                             // 4 j rows of D (64 floats each)
            kp += 256;                            // 4 rows of proj (256 floats each)

            float p = q0.x * k0.x + q0.y * k0.y;
            p = fmaf(q0.z, k0.z, p);
            p = fmaf(q0.w, k0.w, p);
            p = fmaf(q1.x, k1.x, p);
            p = fmaf(q1.y, k1.y, p);
            p = fmaf(q1.z, k1.z, p);
            p = fmaf(q1.w, k1.w, p);
            p = fmaf(r0.x, d0.x, p);
            p = fmaf(r0.y, d0.y, p);
            p = fmaf(r0.z, d0.z, p);
            p = fmaf(r0.w, d0.w, p);
            p = fmaf(r1.x, d1.x, p);
            p = fmaf(r1.y, d1.y, p);
            p = fmaf(r1.z, d1.z, p);
            p = fmaf(r1.w, d1.w, p);

            p += __shfl_xor_sync(0xffffffffu, p, 4);
            p += __shfl_xor_sync(0xffffffffu, p, 2);
            p += __shfl_xor_sync(0xffffffffu, p, 1);
            if (rq == 0) {
                int j = j0 + 4 * t + jj;
                wsh[(j << 2) + g] = p * scale;
            }
        }
    }
    __syncthreads();

    // ---------------- Phase 2: softmax, 4 rows in parallel ----------------
    {
        const int gg = tid >> 7;                  // row handled by this group
        const int tl = tid & 127;
        const int wg = (tid >> 5) & 3;            // warp within group

        float m = -1e30f;
        #pragma unroll
        for (int u = 0; u < 16; u++)
            m = fmaxf(m, wsh[((tl + u * 128) << 2) + gg]);
        #pragma unroll
        for (int o = 16; o; o >>= 1)
            m = fmaxf(m, __shfl_xor_sync(0xffffffffu, m, o));
        if (lane == 0) red[gg][wg] = m;
        __syncthreads();
        m = fmaxf(fmaxf(red[gg][0], red[gg][1]), fmaxf(red[gg][2], red[gg][3]));

        float s = 0.f;
        #pragma unroll
        for (int u = 0; u < 16; u++) {
            int idx = ((tl + u * 128) << 2) + gg;
            float e = __expf(wsh[idx] - m);
            wsh[idx] = e;
            s += e;
        }
        #pragma unroll
        for (int o = 16; o; o >>= 1)
            s += __shfl_xor_sync(0xffffffffu, s, o);
        __syncthreads();
        if (lane == 0) red[gg][4 + wg] = s;
        __syncthreads();
        if (tid < 4)
            inv4[tid] = 1.0f / (red[tid][4] + red[tid][5] + red[tid][6] + red[tid][7]);
        __syncthreads();
    }

    // ---------------- Phase 3: attn @ V ----------------
    {
        const int d = tid & 63;
        const int h = tid >> 6;                   // 8 j-interleaved groups
        float a0 = 0.f, a1 = 0.f, a2 = 0.f, a3 = 0.f;
        const float* Vp = proj + 128 + d;
        #pragma unroll 4
        for (int j = h; j < NN; j += 8) {
            float  v = __ldg(Vp + (size_t)j * DIN);
            float4 e = *(const float4*)(wsh + (j << 2));
            a0 = fmaf(e.x, v, a0);
            a1 = fmaf(e.y, v, a1);
            a2 = fmaf(e.z, v, a2);
            a3 = fmaf(e.w, v, a3);
        }
        __syncthreads();                          // done reading weights
        wsh[((h << 2) + 0) * 64 + d] = a0;
        wsh[((h << 2) + 1) * 64 + d] = a1;
        wsh[((h << 2) + 2) * 64 + d] = a2;
        wsh[((h << 2) + 3) * 64 + d] = a3;
        __syncthreads();
        if (tid < 256) {
            const int g2 = tid >> 6, d2 = tid & 63;
            float r = 0.f;
            #pragma unroll
            for (int hh = 0; hh < 8; hh++)
                r += wsh[((hh << 2) + g2) * 64 + d2];
            out[(size_t)(i0 + g2) * 64 + d2] = r * inv4[g2];
        }
    }
}

// ---------------------------------------------------------------------------
extern "C" void kernel_launch(void* const* d_in, const int* in_sizes, int n_in,
                              void* d_out, int out_size)
{
    (void)out_size;
    const float *H = nullptr, *Dm = nullptr, *Wp = nullptr;
    for (int i = 0; i < n_in; i++) {
        if      (in_sizes[i] == NN * DIN)  H  = (const float*)d_in[i];
        else if (in_sizes[i] == DIN * DIN) Wp = (const float*)d_in[i];
        else                               Dm = (const float*)d_in[i];
    }

    float* proj = nullptr;
    cudaGetSymbolAddress((void**)&proj, g_proj);

    // 1) proj = H @ W^T   (2048 x 256) — 64x32 tiles -> 256 blocks
    gemm_nt32<<<dim3(DIN / 32, NN / 64), 256>>>(H, DIN, Wp, DIN, proj, DIN, DIN, 1.0f);
    // 2) fused QK^T + RD + softmax + @V  — single wave: 512 blocks @ 4/SM
    attn_main<<<NN / 4, 512>>>(Dm, proj, (float*)d_out);
}